// round 1
// baseline (speedup 1.0000x reference)
#include <cuda_runtime.h>

#define H_ 16
#define D_ 1024
#define DK 64
#define B_ 2
#define S_ 2048
#define M_ (B_ * S_)   // 4096

// Scratch (device globals: allocation-free per harness rules)
__device__ float g_Q[B_ * H_ * S_ * DK];   // [B,H,S,dk], pre-scaled by 1/sqrt(dk)
__device__ float g_K[B_ * H_ * S_ * DK];
__device__ float g_V[B_ * H_ * S_ * DK];
__device__ float g_atn[B_ * S_ * D_];      // attention output, channel = d*H + h

// ---------------------------------------------------------------------------
// Tiled SGEMM: C[M,N] = A[M,K] @ W[N,K]^T   (both row-major, K contiguous)
// BM=BN=128, BK=8, 256 threads, 8x8 per thread.
// MODE 0: plain store to C.
// MODE 1: QKV scatter epilogue into g_Q/g_K/g_V (head de-interleave, Q scaled).
// ---------------------------------------------------------------------------
template <int MODE>
__global__ __launch_bounds__(256) void gemm_kernel(
    const float* __restrict__ A, const float* __restrict__ W,
    float* __restrict__ C, int M, int N, int K)
{
    __shared__ float As[8][132];
    __shared__ float Bs[8][132];

    const int t  = threadIdx.x;
    const int tx = t & 15;
    const int ty = t >> 4;
    const int m0 = blockIdx.y * 128;
    const int n0 = blockIdx.x * 128;

    float acc[8][8];
#pragma unroll
    for (int i = 0; i < 8; i++)
#pragma unroll
        for (int j = 0; j < 8; j++) acc[i][j] = 0.0f;

    const int lrow = t >> 1;          // 0..127
    const int lkq  = (t & 1) * 4;     // 0 or 4

    const float* Aptr = A + (size_t)(m0 + lrow) * K + lkq;
    const float* Wptr = W + (size_t)(n0 + lrow) * K + lkq;

    for (int k0 = 0; k0 < K; k0 += 8) {
        float4 av = *reinterpret_cast<const float4*>(Aptr + k0);
        float4 wv = *reinterpret_cast<const float4*>(Wptr + k0);
        __syncthreads();   // previous tile fully consumed
        As[lkq + 0][lrow] = av.x;
        As[lkq + 1][lrow] = av.y;
        As[lkq + 2][lrow] = av.z;
        As[lkq + 3][lrow] = av.w;
        Bs[lkq + 0][lrow] = wv.x;
        Bs[lkq + 1][lrow] = wv.y;
        Bs[lkq + 2][lrow] = wv.z;
        Bs[lkq + 3][lrow] = wv.w;
        __syncthreads();

#pragma unroll
        for (int kk = 0; kk < 8; kk++) {
            float4 a0 = *reinterpret_cast<const float4*>(&As[kk][ty * 4]);
            float4 a1 = *reinterpret_cast<const float4*>(&As[kk][ty * 4 + 64]);
            float4 b0 = *reinterpret_cast<const float4*>(&Bs[kk][tx * 4]);
            float4 b1 = *reinterpret_cast<const float4*>(&Bs[kk][tx * 4 + 64]);
            float a[8] = {a0.x, a0.y, a0.z, a0.w, a1.x, a1.y, a1.z, a1.w};
            float b[8] = {b0.x, b0.y, b0.z, b0.w, b1.x, b1.y, b1.z, b1.w};
#pragma unroll
            for (int i = 0; i < 8; i++)
#pragma unroll
                for (int j = 0; j < 8; j++) acc[i][j] += a[i] * b[j];
        }
    }

    int rr[8], cc[8];
#pragma unroll
    for (int i = 0; i < 4; i++) {
        rr[i]     = m0 + ty * 4 + i;
        rr[i + 4] = rr[i] + 64;
        cc[i]     = n0 + tx * 4 + i;
        cc[i + 4] = cc[i] + 64;
    }

    if (MODE == 0) {
#pragma unroll
        for (int i = 0; i < 8; i++)
#pragma unroll
            for (int j = 0; j < 8; j++)
                C[(size_t)rr[i] * N + cc[j]] = acc[i][j];
    } else {
        const float qscale = 0.125f;  // 1/sqrt(64)
#pragma unroll
        for (int i = 0; i < 8; i++) {
            const int s = rr[i] & (S_ - 1);
            const int b = rr[i] >> 11;
#pragma unroll
            for (int j = 0; j < 8; j++) {
                const int c   = cc[j];
                const int sel = c >> 10;        // 0=Q, 1=K, 2=V
                const int e   = c & 1023;
                const int h   = e & 15;
                const int d   = e >> 4;
                const int idx = (((b * H_ + h) * S_ + s) * DK) + d;
                float v = acc[i][j];
                if (sel == 0)      g_Q[idx] = v * qscale;
                else if (sel == 1) g_K[idx] = v;
                else               g_V[idx] = v;
            }
        }
    }
}

// ---------------------------------------------------------------------------
// Flash attention: one block per (q-tile of 64, head, batch).
// 256 threads, 4x4 microtiles. Online softmax. Mask is all-true (ignored).
// smem: Qt[64][68] (d-major), KP[64][68] (Kt d-major, reused as P r-major),
//       Vs[64][68] (c-major). 52224 bytes dynamic.
// ---------------------------------------------------------------------------
#define ASTR 68
__global__ __launch_bounds__(256) void attn_kernel()
{
    extern __shared__ float sm[];
    float* Qt = sm;                  // [d][r]
    float* KP = sm + 64 * ASTR;      // K: [d][c]; later P: [r][c]
    float* Vs = sm + 2 * 64 * ASTR;  // [c][d]

    const int t  = threadIdx.x;
    const int tx = t & 15;
    const int ty = t >> 4;
    const int qt = blockIdx.x;
    const int h  = blockIdx.y;
    const int b  = blockIdx.z;
    const int bh = b * H_ + h;

    const float* Qg = g_Q + ((size_t)bh * S_ + qt * 64) * DK;
    const float* Kg = g_K + (size_t)bh * S_ * DK;
    const float* Vg = g_V + (size_t)bh * S_ * DK;

    // Load Q tile transposed: Qt[d][r]
    {
        const int r  = t >> 2;
        const int dq = (t & 3) * 16;
        const float* src = Qg + r * DK + dq;
#pragma unroll
        for (int u = 0; u < 4; u++) {
            float4 v = *reinterpret_cast<const float4*>(src + u * 4);
            Qt[(dq + u * 4 + 0) * ASTR + r] = v.x;
            Qt[(dq + u * 4 + 1) * ASTR + r] = v.y;
            Qt[(dq + u * 4 + 2) * ASTR + r] = v.z;
            Qt[(dq + u * 4 + 3) * ASTR + r] = v.w;
        }
    }

    float m_i[4], l_i[4], o[4][4];
#pragma unroll
    for (int i = 0; i < 4; i++) {
        m_i[i] = -1e30f;
        l_i[i] = 0.0f;
#pragma unroll
        for (int j = 0; j < 4; j++) o[i][j] = 0.0f;
    }

    for (int jt = 0; jt < S_ / 64; jt++) {
        __syncthreads();  // previous P·V reads complete (also covers Qt on iter 0)

        // Load K transposed + V natural
        {
            const int r  = t >> 2;
            const int dq = (t & 3) * 16;
            const float* kr = Kg + (jt * 64 + r) * DK + dq;
            const float* vr = Vg + (jt * 64 + r) * DK + dq;
#pragma unroll
            for (int u = 0; u < 4; u++) {
                float4 kv = *reinterpret_cast<const float4*>(kr + u * 4);
                KP[(dq + u * 4 + 0) * ASTR + r] = kv.x;
                KP[(dq + u * 4 + 1) * ASTR + r] = kv.y;
                KP[(dq + u * 4 + 2) * ASTR + r] = kv.z;
                KP[(dq + u * 4 + 3) * ASTR + r] = kv.w;
                float4 vv = *reinterpret_cast<const float4*>(vr + u * 4);
                *reinterpret_cast<float4*>(&Vs[r * ASTR + dq + u * 4]) = vv;
            }
        }
        __syncthreads();

        // S = Q @ K^T  (Q already scaled)
        float sc[4][4];
#pragma unroll
        for (int i = 0; i < 4; i++)
#pragma unroll
            for (int j = 0; j < 4; j++) sc[i][j] = 0.0f;

#pragma unroll 4
        for (int d = 0; d < 64; d++) {
            float4 a = *reinterpret_cast<const float4*>(&Qt[d * ASTR + ty * 4]);
            float4 bq = *reinterpret_cast<const float4*>(&KP[d * ASTR + tx * 4]);
            float av[4] = {a.x, a.y, a.z, a.w};
            float bv[4] = {bq.x, bq.y, bq.z, bq.w};
#pragma unroll
            for (int i = 0; i < 4; i++)
#pragma unroll
                for (int j = 0; j < 4; j++) sc[i][j] += av[i] * bv[j];
        }
        __syncthreads();  // all Kt reads done; KP reusable as P

        // Online softmax + write P into KP (natural [r][c])
#pragma unroll
        for (int i = 0; i < 4; i++) {
            float rm = sc[i][0];
#pragma unroll
            for (int j = 1; j < 4; j++) rm = fmaxf(rm, sc[i][j]);
#pragma unroll
            for (int off = 1; off < 16; off <<= 1)
                rm = fmaxf(rm, __shfl_xor_sync(0xffffffffu, rm, off));
            const float mn = fmaxf(m_i[i], rm);
            const float corr = __expf(m_i[i] - mn);
            float rs = 0.0f;
#pragma unroll
            for (int j = 0; j < 4; j++) {
                float p = __expf(sc[i][j] - mn);
                sc[i][j] = p;
                rs += p;
            }
#pragma unroll
            for (int off = 1; off < 16; off <<= 1)
                rs += __shfl_xor_sync(0xffffffffu, rs, off);
            l_i[i] = l_i[i] * corr + rs;
            m_i[i] = mn;
#pragma unroll
            for (int j = 0; j < 4; j++) o[i][j] *= corr;
            *reinterpret_cast<float4*>(&KP[(ty * 4 + i) * ASTR + tx * 4]) =
                make_float4(sc[i][0], sc[i][1], sc[i][2], sc[i][3]);
        }
        __syncthreads();

        // O += P @ V
#pragma unroll 4
        for (int c = 0; c < 64; c++) {
            float p0 = KP[(ty * 4 + 0) * ASTR + c];
            float p1 = KP[(ty * 4 + 1) * ASTR + c];
            float p2 = KP[(ty * 4 + 2) * ASTR + c];
            float p3 = KP[(ty * 4 + 3) * ASTR + c];
            float4 v = *reinterpret_cast<const float4*>(&Vs[c * ASTR + tx * 4]);
            o[0][0] += p0 * v.x; o[0][1] += p0 * v.y; o[0][2] += p0 * v.z; o[0][3] += p0 * v.w;
            o[1][0] += p1 * v.x; o[1][1] += p1 * v.y; o[1][2] += p1 * v.z; o[1][3] += p1 * v.w;
            o[2][0] += p2 * v.x; o[2][1] += p2 * v.y; o[2][2] += p2 * v.z; o[2][3] += p2 * v.w;
            o[3][0] += p3 * v.x; o[3][1] += p3 * v.y; o[3][2] += p3 * v.z; o[3][3] += p3 * v.w;
        }
    }

    // Epilogue: atn[b, s, d*H + h] = O / l
#pragma unroll
    for (int i = 0; i < 4; i++) {
        const float inv = 1.0f / l_i[i];
        const int s = qt * 64 + ty * 4 + i;
        float* dst = g_atn + ((size_t)(b * S_ + s)) * D_;
#pragma unroll
        for (int j = 0; j < 4; j++) {
            const int dd = tx * 4 + j;
            dst[dd * H_ + h] = o[i][j] * inv;
        }
    }
}

// ---------------------------------------------------------------------------
extern "C" void kernel_launch(void* const* d_in, const int* in_sizes, int n_in,
                              void* d_out, int out_size)
{
    const float* xs    = (const float*)d_in[0];
    // d_in[1] = mask (all true; reference masks nothing) — unused
    const float* w_qkv = (const float*)d_in[2];
    const float* w_out = (const float*)d_in[3];
    float* out = (float*)d_out;

    float* atn_ptr;
    cudaGetSymbolAddress((void**)&atn_ptr, g_atn);

    // 1) QKV projection with scatter epilogue
    {
        dim3 grid(3 * D_ / 128, M_ / 128);  // (24, 32)
        gemm_kernel<1><<<grid, 256>>>(xs, w_qkv, nullptr, M_, 3 * D_, D_);
    }

    // 2) Flash attention
    {
        const int smem = 3 * 64 * ASTR * (int)sizeof(float);  // 52224 B
        cudaFuncSetAttribute(attn_kernel,
                             cudaFuncAttributeMaxDynamicSharedMemorySize, smem);
        dim3 grid(S_ / 64, H_, B_);  // (32, 16, 2)
        attn_kernel<<<grid, 256, smem>>>();
    }

    // 3) Output projection
    {
        dim3 grid(D_ / 128, M_ / 128);  // (8, 32)
        gemm_kernel<0><<<grid, 256>>>(atn_ptr, w_out, out, M_, D_, D_);
    }
}

// round 2
// speedup vs baseline: 1.4033x; 1.4033x over previous
#include <cuda_runtime.h>
#include <cstdint>

#define H_ 16
#define D_ 1024
#define DK 64
#define B_ 2
#define S_ 2048
#define M_ (B_ * S_)   // 4096

// Scratch (device globals)
__device__ float g_Qhi[B_ * H_ * S_ * DK];   // tf32-exact, pre-scaled 1/8
__device__ float g_Qlo[B_ * H_ * S_ * DK];   // residual
__device__ float g_Khi[B_ * H_ * S_ * DK];
__device__ float g_Klo[B_ * H_ * S_ * DK];
__device__ float g_Vt [B_ * H_ * DK * S_];   // V transposed [b,h,d,s], tf32-rounded
__device__ float g_atn[B_ * S_ * D_];        // attention out, channel = d*H + h

// ---------------------------------------------------------------------------
__device__ __forceinline__ uint32_t f2tf(float x) {
    uint32_t r;
    asm("cvt.rna.tf32.f32 %0, %1;" : "=r"(r) : "f"(x));
    return r;
}

__device__ __forceinline__ void mma_tf32(float c[4], const uint32_t a[4],
                                         const uint32_t b[2]) {
    asm volatile(
        "mma.sync.aligned.m16n8k8.row.col.f32.tf32.tf32.f32 "
        "{%0,%1,%2,%3}, {%4,%5,%6,%7}, {%8,%9}, {%0,%1,%2,%3};\n"
        : "+f"(c[0]), "+f"(c[1]), "+f"(c[2]), "+f"(c[3])
        : "r"(a[0]), "r"(a[1]), "r"(a[2]), "r"(a[3]), "r"(b[0]), "r"(b[1]));
}

// ---------------------------------------------------------------------------
// tf32 split-3 GEMM: C[M,N] = A[M,K] @ W[N,K]^T (row-major, K contiguous)
// Block 128x128, 256 thr, 8 warps (4M x 2N), warp tile 32x64, BK=16.
// MODE 0: plain store. MODE 1: QKV scatter (Q/K hi-lo split, V transposed).
// ---------------------------------------------------------------------------
#define GKS 20  // smem k-stride (16 + 4 pad): conflict-free frag LDS
template <int MODE>
__global__ __launch_bounds__(256) void gemm_tf32(
    const float* __restrict__ A, const float* __restrict__ W,
    float* __restrict__ C, int M, int N, int K)
{
    __shared__ float As[128 * GKS];
    __shared__ float Bs[128 * GKS];

    const int t = threadIdx.x;
    const int lane = t & 31, wid = t >> 5;
    const int g = lane >> 2, l4 = lane & 3;
    const int warpM = wid >> 1, warpN = wid & 1;
    const int m0 = blockIdx.y * 128, n0 = blockIdx.x * 128;

    float c[2][8][4];
#pragma unroll
    for (int i = 0; i < 2; i++)
#pragma unroll
        for (int j = 0; j < 8; j++)
#pragma unroll
            for (int v = 0; v < 4; v++) c[i][j][v] = 0.0f;

    const int lm = t >> 1;
    const int lk = (t & 1) * 8;
    const float* Ap = A + (size_t)(m0 + lm) * K + lk;
    const float* Wp = W + (size_t)(n0 + lm) * K + lk;

    for (int k0 = 0; k0 < K; k0 += 16) {
        float4 a0 = *(const float4*)(Ap + k0);
        float4 a1 = *(const float4*)(Ap + k0 + 4);
        float4 w0 = *(const float4*)(Wp + k0);
        float4 w1 = *(const float4*)(Wp + k0 + 4);
        __syncthreads();
        *(float4*)&As[lm * GKS + lk]     = a0;
        *(float4*)&As[lm * GKS + lk + 4] = a1;
        *(float4*)&Bs[lm * GKS + lk]     = w0;
        *(float4*)&Bs[lm * GKS + lk + 4] = w1;
        __syncthreads();

#pragma unroll
        for (int ks = 0; ks < 2; ks++) {
            const int kb = ks * 8;
            uint32_t ahi[2][4], alo[2][4];
            uint32_t bhi[8][2], blo[8][2];
#pragma unroll
            for (int ma = 0; ma < 2; ma++) {
                const int rb = warpM * 32 + ma * 16;
                float v0 = As[(rb + g) * GKS + kb + l4];
                float v1 = As[(rb + g + 8) * GKS + kb + l4];
                float v2 = As[(rb + g) * GKS + kb + l4 + 4];
                float v3 = As[(rb + g + 8) * GKS + kb + l4 + 4];
                ahi[ma][0] = f2tf(v0); alo[ma][0] = __float_as_uint(v0 - __uint_as_float(ahi[ma][0]));
                ahi[ma][1] = f2tf(v1); alo[ma][1] = __float_as_uint(v1 - __uint_as_float(ahi[ma][1]));
                ahi[ma][2] = f2tf(v2); alo[ma][2] = __float_as_uint(v2 - __uint_as_float(ahi[ma][2]));
                ahi[ma][3] = f2tf(v3); alo[ma][3] = __float_as_uint(v3 - __uint_as_float(ahi[ma][3]));
            }
#pragma unroll
            for (int na = 0; na < 8; na++) {
                const int cb = warpN * 64 + na * 8;
                float v0 = Bs[(cb + g) * GKS + kb + l4];
                float v1 = Bs[(cb + g) * GKS + kb + l4 + 4];
                bhi[na][0] = f2tf(v0); blo[na][0] = __float_as_uint(v0 - __uint_as_float(bhi[na][0]));
                bhi[na][1] = f2tf(v1); blo[na][1] = __float_as_uint(v1 - __uint_as_float(bhi[na][1]));
            }
#pragma unroll
            for (int ma = 0; ma < 2; ma++)
#pragma unroll
                for (int na = 0; na < 8; na++) {
                    mma_tf32(c[ma][na], ahi[ma], bhi[na]);
                    mma_tf32(c[ma][na], ahi[ma], blo[na]);
                    mma_tf32(c[ma][na], alo[ma], bhi[na]);
                }
        }
    }

    // Epilogue
#pragma unroll
    for (int ma = 0; ma < 2; ma++)
#pragma unroll
        for (int na = 0; na < 8; na++)
#pragma unroll
            for (int v = 0; v < 4; v++) {
                const int m = m0 + warpM * 32 + ma * 16 + g + ((v >= 2) ? 8 : 0);
                const int n = n0 + warpN * 64 + na * 8 + 2 * l4 + (v & 1);
                const float val = c[ma][na][v];
                if (MODE == 0) {
                    C[(size_t)m * N + n] = val;
                } else {
                    const int s = m & (S_ - 1), b = m >> 11;
                    const int sel = n >> 10, e = n & 1023;
                    const int hh = e & 15, d = e >> 4;
                    if (sel == 2) {
                        g_Vt[(((size_t)(b * H_ + hh)) * DK + d) * S_ + s] =
                            __uint_as_float(f2tf(val));
                    } else {
                        const size_t idx = (((size_t)(b * H_ + hh)) * S_ + s) * DK + d;
                        if (sel == 0) {
                            const float q = val * 0.125f;
                            const uint32_t hw = f2tf(q);
                            g_Qhi[idx] = __uint_as_float(hw);
                            g_Qlo[idx] = q - __uint_as_float(hw);
                        } else {
                            const uint32_t hw = f2tf(val);
                            g_Khi[idx] = __uint_as_float(hw);
                            g_Klo[idx] = val - __uint_as_float(hw);
                        }
                    }
                }
            }
}

// ---------------------------------------------------------------------------
// Flash attention with tf32 mma. q-tile 128, kv-tile 64.
// 8 warps, each owns 16 q rows -> warp-local softmax (no cross-warp sync).
// S = Q@K^T split-3 (exact); P@V single-pass tf32 (P rounded rna, V pre-rounded).
// smem: Khi[64][68], Klo[64][68], Vt[64][68] (d-major), Ps[128][68]. 87040 B.
// ---------------------------------------------------------------------------
#define KSTR 68
__global__ __launch_bounds__(256, 1) void attn_mma()
{
    extern __shared__ float sm[];
    float* Khi = sm;
    float* Klo = sm + 64 * KSTR;
    float* Vs  = sm + 2 * 64 * KSTR;   // V^T tile: [d][kv]
    float* Ps  = sm + 3 * 64 * KSTR;   // P tile: [q(128)][kv(64)]

    const int t = threadIdx.x, lane = t & 31, wid = t >> 5;
    const int g = lane >> 2, l4 = lane & 3;
    const int qt = blockIdx.x, hh = blockIdx.y, b = blockIdx.z;
    const int bhid = b * H_ + hh;
    const int q0 = qt * 128;
    const int wq = wid * 16;

    // Preload this warp's Q fragments (8 k-atoms, hi+lo)
    uint32_t qhi[8][4], qlo[8][4];
    {
        const float* Qh = g_Qhi + ((size_t)bhid * S_ + q0 + wq) * DK;
        const float* Ql = g_Qlo + ((size_t)bhid * S_ + q0 + wq) * DK;
#pragma unroll
        for (int kk = 0; kk < 8; kk++) {
            const int cb = kk * 8 + l4;
            qhi[kk][0] = __float_as_uint(Qh[g * DK + cb]);
            qhi[kk][1] = __float_as_uint(Qh[(g + 8) * DK + cb]);
            qhi[kk][2] = __float_as_uint(Qh[g * DK + cb + 4]);
            qhi[kk][3] = __float_as_uint(Qh[(g + 8) * DK + cb + 4]);
            qlo[kk][0] = __float_as_uint(Ql[g * DK + cb]);
            qlo[kk][1] = __float_as_uint(Ql[(g + 8) * DK + cb]);
            qlo[kk][2] = __float_as_uint(Ql[g * DK + cb + 4]);
            qlo[kk][3] = __float_as_uint(Ql[(g + 8) * DK + cb + 4]);
        }
    }

    float o[8][4];
#pragma unroll
    for (int na = 0; na < 8; na++)
#pragma unroll
        for (int v = 0; v < 4; v++) o[na][v] = 0.0f;
    float m0r = -1e30f, m1r = -1e30f, l0r = 0.0f, l1r = 0.0f;

    for (int jt = 0; jt < S_ / 64; jt++) {
        __syncthreads();   // smem tiles free to overwrite
        {
            const int r = t >> 2, cq = (t & 3) * 16;
            const float* kh = g_Khi + ((size_t)bhid * S_ + jt * 64 + r) * DK + cq;
            const float* kl = g_Klo + ((size_t)bhid * S_ + jt * 64 + r) * DK + cq;
            const float* vt = g_Vt + ((size_t)bhid * DK + r) * S_ + jt * 64 + cq;
#pragma unroll
            for (int u = 0; u < 4; u++) {
                *(float4*)&Khi[r * KSTR + cq + 4 * u] = *(const float4*)(kh + 4 * u);
                *(float4*)&Klo[r * KSTR + cq + 4 * u] = *(const float4*)(kl + 4 * u);
                *(float4*)&Vs [r * KSTR + cq + 4 * u] = *(const float4*)(vt + 4 * u);
            }
        }
        __syncthreads();

        // S = Q @ K^T (split-3)
        float sc[8][4];
#pragma unroll
        for (int na = 0; na < 8; na++)
#pragma unroll
            for (int v = 0; v < 4; v++) sc[na][v] = 0.0f;

#pragma unroll
        for (int kk = 0; kk < 8; kk++) {
#pragma unroll
            for (int na = 0; na < 8; na++) {
                const int rowb = (na * 8 + g) * KSTR + kk * 8 + l4;
                uint32_t bh_[2], bl_[2];
                bh_[0] = __float_as_uint(Khi[rowb]);
                bh_[1] = __float_as_uint(Khi[rowb + 4]);
                bl_[0] = __float_as_uint(Klo[rowb]);
                bl_[1] = __float_as_uint(Klo[rowb + 4]);
                mma_tf32(sc[na], qhi[kk], bh_);
                mma_tf32(sc[na], qhi[kk], bl_);
                mma_tf32(sc[na], qlo[kk], bh_);
            }
        }

        // Warp-local online softmax (rows wq+g and wq+g+8)
        float rm0 = -1e30f, rm1 = -1e30f;
#pragma unroll
        for (int na = 0; na < 8; na++) {
            rm0 = fmaxf(rm0, fmaxf(sc[na][0], sc[na][1]));
            rm1 = fmaxf(rm1, fmaxf(sc[na][2], sc[na][3]));
        }
#pragma unroll
        for (int off = 1; off < 4; off <<= 1) {
            rm0 = fmaxf(rm0, __shfl_xor_sync(0xffffffffu, rm0, off));
            rm1 = fmaxf(rm1, __shfl_xor_sync(0xffffffffu, rm1, off));
        }
        const float mn0 = fmaxf(m0r, rm0), mn1 = fmaxf(m1r, rm1);
        const float cor0 = __expf(m0r - mn0), cor1 = __expf(m1r - mn1);
        float rs0 = 0.0f, rs1 = 0.0f;
#pragma unroll
        for (int na = 0; na < 8; na++) {
            const float p0 = __expf(sc[na][0] - mn0);
            const float p1 = __expf(sc[na][1] - mn0);
            const float p2 = __expf(sc[na][2] - mn1);
            const float p3 = __expf(sc[na][3] - mn1);
            rs0 += p0 + p1;
            rs1 += p2 + p3;
            const int col = na * 8 + 2 * l4;
            *(float2*)&Ps[(wq + g) * KSTR + col] =
                make_float2(__uint_as_float(f2tf(p0)), __uint_as_float(f2tf(p1)));
            *(float2*)&Ps[(wq + g + 8) * KSTR + col] =
                make_float2(__uint_as_float(f2tf(p2)), __uint_as_float(f2tf(p3)));
        }
#pragma unroll
        for (int off = 1; off < 4; off <<= 1) {
            rs0 += __shfl_xor_sync(0xffffffffu, rs0, off);
            rs1 += __shfl_xor_sync(0xffffffffu, rs1, off);
        }
        l0r = l0r * cor0 + rs0;
        l1r = l1r * cor1 + rs1;
        m0r = mn0; m1r = mn1;
#pragma unroll
        for (int na = 0; na < 8; na++) {
            o[na][0] *= cor0; o[na][1] *= cor0;
            o[na][2] *= cor1; o[na][3] *= cor1;
        }
        __syncwarp();   // Ps region is warp-private: order writes before reads

        // O += P @ V  (single-pass tf32)
#pragma unroll
        for (int kk = 0; kk < 8; kk++) {
            uint32_t pa[4];
            pa[0] = __float_as_uint(Ps[(wq + g) * KSTR + kk * 8 + l4]);
            pa[1] = __float_as_uint(Ps[(wq + g + 8) * KSTR + kk * 8 + l4]);
            pa[2] = __float_as_uint(Ps[(wq + g) * KSTR + kk * 8 + l4 + 4]);
            pa[3] = __float_as_uint(Ps[(wq + g + 8) * KSTR + kk * 8 + l4 + 4]);
#pragma unroll
            for (int na = 0; na < 8; na++) {
                uint32_t vb[2];
                vb[0] = __float_as_uint(Vs[(na * 8 + g) * KSTR + kk * 8 + l4]);
                vb[1] = __float_as_uint(Vs[(na * 8 + g) * KSTR + kk * 8 + l4 + 4]);
                mma_tf32(o[na], pa, vb);
            }
        }
    }

    // Epilogue: atn[b, s, d*H + h] = O / l
    {
        const float inv0 = 1.0f / l0r, inv1 = 1.0f / l1r;
        const int s0 = q0 + wq + g, s1 = s0 + 8;
        float* d0 = g_atn + ((size_t)(b * S_ + s0)) * D_;
        float* d1 = g_atn + ((size_t)(b * S_ + s1)) * D_;
#pragma unroll
        for (int na = 0; na < 8; na++) {
            const int dd = na * 8 + 2 * l4;
            d0[dd * H_ + hh]       = o[na][0] * inv0;
            d0[(dd + 1) * H_ + hh] = o[na][1] * inv0;
            d1[dd * H_ + hh]       = o[na][2] * inv1;
            d1[(dd + 1) * H_ + hh] = o[na][3] * inv1;
        }
    }
}

// ---------------------------------------------------------------------------
extern "C" void kernel_launch(void* const* d_in, const int* in_sizes, int n_in,
                              void* d_out, int out_size)
{
    const float* xs    = (const float*)d_in[0];
    // d_in[1] = mask (all-true) — unused
    const float* w_qkv = (const float*)d_in[2];
    const float* w_out = (const float*)d_in[3];
    float* out = (float*)d_out;

    float* atn_ptr;
    cudaGetSymbolAddress((void**)&atn_ptr, g_atn);

    // 1) QKV projection (split-3 tf32) with scatter epilogue
    {
        dim3 grid(3 * D_ / 128, M_ / 128);  // (24, 32)
        gemm_tf32<1><<<grid, 256>>>(xs, w_qkv, nullptr, M_, 3 * D_, D_);
    }

    // 2) Flash attention (tf32 mma)
    {
        const int smem = (3 * 64 * KSTR + 128 * KSTR) * (int)sizeof(float); // 87040
        cudaFuncSetAttribute(attn_mma,
                             cudaFuncAttributeMaxDynamicSharedMemorySize, smem);
        dim3 grid(S_ / 128, H_, B_);  // (16, 16, 2)
        attn_mma<<<grid, 256, smem>>>();
    }

    // 3) Output projection (split-3 tf32)
    {
        dim3 grid(D_ / 128, M_ / 128);  // (8, 32)
        gemm_tf32<0><<<grid, 256>>>(atn_ptr, w_out, out, M_, D_, D_);
    }
}

// round 3
// speedup vs baseline: 1.8804x; 1.3400x over previous
#include <cuda_runtime.h>
#include <cuda_bf16.h>
#include <cstdint>

#define H_ 16
#define D_ 1024
#define DK 64
#define B_ 2
#define S_ 2048
#define M_ (B_ * S_)   // 4096

typedef __nv_bfloat16 bf16;

// ---------------- device scratch (no allocs allowed) ----------------
__device__ bf16 g_Xh [M_ * D_],     g_Xl [M_ * D_];      // xs split
__device__ bf16 g_Wqh[3 * D_ * D_], g_Wql[3 * D_ * D_];  // w_qkv split
__device__ bf16 g_Woh[D_ * D_],     g_Wol[D_ * D_];      // w_out split
__device__ bf16 g_Aih[M_ * D_],     g_Ail[M_ * D_];      // atn split
__device__ bf16 g_Qh[B_*H_*S_*DK],  g_Ql[B_*H_*S_*DK];   // Q pre-scaled 1/8
__device__ bf16 g_Kh[B_*H_*S_*DK],  g_Kl[B_*H_*S_*DK];
__device__ bf16 g_Vh[B_*H_*DK*S_],  g_Vl[B_*H_*DK*S_];   // V transposed [b,h,d,s]
__device__ float g_atn[M_ * D_];                          // attn out, ch = d*H+h

// ---------------- helpers ----------------
__device__ __forceinline__ void bsplit(float x, bf16& h, bf16& l) {
    h = __float2bfloat16(x);
    l = __float2bfloat16(x - __bfloat162float(h));
}
__device__ __forceinline__ uint32_t pk(bf16 a, bf16 b) {
    return (uint32_t)__bfloat16_as_ushort(a) |
           ((uint32_t)__bfloat16_as_ushort(b) << 16);
}
__device__ __forceinline__ uint32_t smem_u32(const void* p) {
    return (uint32_t)__cvta_generic_to_shared(p);
}
__device__ __forceinline__ void ldsm4(uint32_t r[4], uint32_t addr) {
    asm volatile("ldmatrix.sync.aligned.m8n8.x4.shared.b16 {%0,%1,%2,%3}, [%4];"
                 : "=r"(r[0]), "=r"(r[1]), "=r"(r[2]), "=r"(r[3]) : "r"(addr));
}
__device__ __forceinline__ void mma_bf16(float c[4], const uint32_t a[4],
                                         uint32_t b0, uint32_t b1) {
    asm volatile(
        "mma.sync.aligned.m16n8k16.row.col.f32.bf16.bf16.f32 "
        "{%0,%1,%2,%3}, {%4,%5,%6,%7}, {%8,%9}, {%0,%1,%2,%3};\n"
        : "+f"(c[0]), "+f"(c[1]), "+f"(c[2]), "+f"(c[3])
        : "r"(a[0]), "r"(a[1]), "r"(a[2]), "r"(a[3]), "r"(b0), "r"(b1));
}
// split-3: acc += hi*hi + hi*lo + lo*hi
__device__ __forceinline__ void mma3(float c[4], const uint32_t ah[4],
                                     const uint32_t al[4],
                                     uint32_t bh0, uint32_t bh1,
                                     uint32_t bl0, uint32_t bl1) {
    mma_bf16(c, ah, bh0, bh1);
    mma_bf16(c, ah, bl0, bl1);
    mma_bf16(c, al, bh0, bh1);
}

// ---------------- pre-split pass (fp32 -> bf16 hi/lo) ----------------
__global__ __launch_bounds__(256) void split_kernel(
    const float* __restrict__ x, bf16* __restrict__ h, bf16* __restrict__ l, int n)
{
    const int i = (blockIdx.x * 256 + threadIdx.x) * 4;
    if (i >= n) return;
    float4 v = *(const float4*)(x + i);
    bf16 h0, h1, h2, h3, l0, l1, l2, l3;
    bsplit(v.x, h0, l0); bsplit(v.y, h1, l1);
    bsplit(v.z, h2, l2); bsplit(v.w, h3, l3);
    *(uint32_t*)(h + i)     = pk(h0, h1);
    *(uint32_t*)(h + i + 2) = pk(h2, h3);
    *(uint32_t*)(l + i)     = pk(l0, l1);
    *(uint32_t*)(l + i + 2) = pk(l2, l3);
}

// ---------------------------------------------------------------------------
// bf16 split-3 GEMM: C[M,N] = A[M,K] @ W[N,K]^T, inputs pre-split bf16 hi/lo.
// Block 128x128, BK=16, 256 thr, 8 warps (4M x 2N), warp tile 32x64.
// MODE 0: store fp32 C.  MODE 1: QKV scatter (Q/K split, V transposed split).
// ---------------------------------------------------------------------------
#define GS 24   // smem k-stride in bf16 (16 + 8 pad): conflict-free ldmatrix
template <int MODE>
__global__ __launch_bounds__(256) void gemm_bf16(
    const bf16* __restrict__ Ah, const bf16* __restrict__ Al,
    const bf16* __restrict__ Bh, const bf16* __restrict__ Bl,
    float* __restrict__ C, int M, int N, int K)
{
    __shared__ __align__(16) bf16 sAh[128 * GS], sAl[128 * GS];
    __shared__ __align__(16) bf16 sBh[128 * GS], sBl[128 * GS];

    const int t = threadIdx.x, lane = t & 31, wid = t >> 5;
    const int g = lane >> 2, l4 = lane & 3;
    const int warpM = wid >> 1, warpN = wid & 1;
    const int m0 = blockIdx.y * 128, n0 = blockIdx.x * 128;

    float c[2][8][4];
#pragma unroll
    for (int i = 0; i < 2; i++)
#pragma unroll
        for (int j = 0; j < 8; j++)
#pragma unroll
            for (int v = 0; v < 4; v++) c[i][j][v] = 0.0f;

    // staging: each thread moves one uint4 (8 bf16) per array per iter
    const int srow = t >> 1, sseg = (t & 1) * 8;
    const bf16* pAh = Ah + (size_t)(m0 + srow) * K + sseg;
    const bf16* pAl = Al + (size_t)(m0 + srow) * K + sseg;
    const bf16* pBh = Bh + (size_t)(n0 + srow) * K + sseg;
    const bf16* pBl = Bl + (size_t)(n0 + srow) * K + sseg;
    bf16* qAh = &sAh[srow * GS + sseg];
    bf16* qAl = &sAl[srow * GS + sseg];
    bf16* qBh = &sBh[srow * GS + sseg];
    bf16* qBl = &sBl[srow * GS + sseg];

    // ldmatrix addresses (fixed per thread)
    const int fr = lane & 15, fc = (lane >> 4) * 8;
    uint32_t aAh[2], aAl[2];
#pragma unroll
    for (int ma = 0; ma < 2; ma++) {
        aAh[ma] = smem_u32(&sAh[(warpM * 32 + ma * 16 + fr) * GS + fc]);
        aAl[ma] = smem_u32(&sAl[(warpM * 32 + ma * 16 + fr) * GS + fc]);
    }
    uint32_t aBh[4], aBl[4];  // [half*2+q]
#pragma unroll
    for (int hq = 0; hq < 4; hq++) {
        const int row = warpN * 64 + hq * 16 + fr;
        aBh[hq] = smem_u32(&sBh[row * GS + fc]);
        aBl[hq] = smem_u32(&sBl[row * GS + fc]);
    }

    for (int k0 = 0; k0 < K; k0 += 16) {
        uint4 va = *(const uint4*)(pAh + k0);
        uint4 vb = *(const uint4*)(pAl + k0);
        uint4 vc = *(const uint4*)(pBh + k0);
        uint4 vd = *(const uint4*)(pBl + k0);
        __syncthreads();
        *(uint4*)qAh = va;
        *(uint4*)qAl = vb;
        *(uint4*)qBh = vc;
        *(uint4*)qBl = vd;
        __syncthreads();

        uint32_t fAh[2][4], fAl[2][4];
        ldsm4(fAh[0], aAh[0]); ldsm4(fAh[1], aAh[1]);
        ldsm4(fAl[0], aAl[0]); ldsm4(fAl[1], aAl[1]);

#pragma unroll
        for (int half = 0; half < 2; half++) {
            uint32_t bh0[4], bh1[4], bl0[4], bl1[4];
            ldsm4(bh0, aBh[half * 2 + 0]); ldsm4(bh1, aBh[half * 2 + 1]);
            ldsm4(bl0, aBl[half * 2 + 0]); ldsm4(bl1, aBl[half * 2 + 1]);
#pragma unroll
            for (int ma = 0; ma < 2; ma++) {
                float* c0 = c[ma][half * 4 + 0];
                float* c1 = c[ma][half * 4 + 1];
                float* c2 = c[ma][half * 4 + 2];
                float* c3 = c[ma][half * 4 + 3];
                mma3(c0, fAh[ma], fAl[ma], bh0[0], bh0[2], bl0[0], bl0[2]);
                mma3(c1, fAh[ma], fAl[ma], bh0[1], bh0[3], bl0[1], bl0[3]);
                mma3(c2, fAh[ma], fAl[ma], bh1[0], bh1[2], bl1[0], bl1[2]);
                mma3(c3, fAh[ma], fAl[ma], bh1[1], bh1[3], bl1[1], bl1[3]);
            }
        }
    }

    // epilogue
#pragma unroll
    for (int ma = 0; ma < 2; ma++)
#pragma unroll
        for (int na = 0; na < 8; na++)
#pragma unroll
            for (int v = 0; v < 4; v++) {
                const int m = m0 + warpM * 32 + ma * 16 + g + ((v >= 2) ? 8 : 0);
                const int n = n0 + warpN * 64 + na * 8 + 2 * l4 + (v & 1);
                const float val = c[ma][na][v];
                if (MODE == 0) {
                    C[(size_t)m * N + n] = val;
                } else {
                    const int s = m & (S_ - 1), b = m >> 11;
                    const int sel = n >> 10, e = n & 1023;
                    const int hh = e & 15, d = e >> 4;
                    bf16 hi, lo;
                    if (sel == 2) {
                        bsplit(val, hi, lo);
                        const size_t vi = (((size_t)(b * H_ + hh)) * DK + d) * S_ + s;
                        g_Vh[vi] = hi; g_Vl[vi] = lo;
                    } else {
                        const size_t idx = (((size_t)(b * H_ + hh)) * S_ + s) * DK + d;
                        if (sel == 0) {
                            bsplit(val * 0.125f, hi, lo);
                            g_Qh[idx] = hi; g_Ql[idx] = lo;
                        } else {
                            bsplit(val, hi, lo);
                            g_Kh[idx] = hi; g_Kl[idx] = lo;
                        }
                    }
                }
            }
}

// ---------------------------------------------------------------------------
// Flash attention, bf16 split-3 mma. q-tile 128 (8 warps x 16 rows), kv-tile 64.
// Q staged once to smem; K/V staged per tile. P fragments built in registers.
// ---------------------------------------------------------------------------
#define AS 72   // smem stride in bf16 (64 + 8 pad)
__global__ __launch_bounds__(256, 2) void attn_bf16()
{
    extern __shared__ __align__(16) char smraw[];
    bf16* sQh = (bf16*)smraw;
    bf16* sQl = sQh + 128 * AS;
    bf16* sKh = sQl + 128 * AS;
    bf16* sKl = sKh + 64 * AS;
    bf16* sVh = sKl + 64 * AS;
    bf16* sVl = sVh + 64 * AS;

    const int t = threadIdx.x, lane = t & 31, wid = t >> 5;
    const int g = lane >> 2, l4 = lane & 3;
    const int qt = blockIdx.x, hh = blockIdx.y, b = blockIdx.z;
    const int bhid = b * H_ + hh;
    const int q0 = qt * 128;
    const int wq = wid * 16;

    // stage Q (hi/lo) once
    {
        const int row = t >> 1, cs = (t & 1) * 32;
        const bf16* gqh = g_Qh + ((size_t)bhid * S_ + q0 + row) * DK + cs;
        const bf16* gql = g_Ql + ((size_t)bhid * S_ + q0 + row) * DK + cs;
#pragma unroll
        for (int u = 0; u < 4; u++) {
            *(uint4*)&sQh[row * AS + cs + 8 * u] = *(const uint4*)(gqh + 8 * u);
            *(uint4*)&sQl[row * AS + cs + 8 * u] = *(const uint4*)(gql + 8 * u);
        }
    }

    // ldmatrix base addresses
    const int fr = lane & 15, fc = (lane >> 4) * 8;
    const uint32_t aQh = smem_u32(&sQh[(wq + fr) * AS + fc]);
    const uint32_t aQl = smem_u32(&sQl[(wq + fr) * AS + fc]);
    uint32_t aKh[4], aKl[4], aVh[4], aVl[4];
#pragma unroll
    for (int hq = 0; hq < 4; hq++) {
        const int row = hq * 16 + fr;
        aKh[hq] = smem_u32(&sKh[row * AS + fc]);
        aKl[hq] = smem_u32(&sKl[row * AS + fc]);
        aVh[hq] = smem_u32(&sVh[row * AS + fc]);
        aVl[hq] = smem_u32(&sVl[row * AS + fc]);
    }

    float o[8][4];
#pragma unroll
    for (int na = 0; na < 8; na++)
#pragma unroll
        for (int v = 0; v < 4; v++) o[na][v] = 0.0f;
    float m0r = -1e30f, m1r = -1e30f, l0r = 0.0f, l1r = 0.0f;

    for (int jt = 0; jt < S_ / 64; jt++) {
        __syncthreads();   // previous tile's reads done (and Q staging on iter 0)
        {
            const int r = t >> 2, cs = (t & 3) * 16;
            const bf16* kh = g_Kh + ((size_t)bhid * S_ + jt * 64 + r) * DK + cs;
            const bf16* kl = g_Kl + ((size_t)bhid * S_ + jt * 64 + r) * DK + cs;
            const bf16* vh = g_Vh + ((size_t)bhid * DK + r) * S_ + jt * 64 + cs;
            const bf16* vl = g_Vl + ((size_t)bhid * DK + r) * S_ + jt * 64 + cs;
#pragma unroll
            for (int u = 0; u < 2; u++) {
                *(uint4*)&sKh[r * AS + cs + 8 * u] = *(const uint4*)(kh + 8 * u);
                *(uint4*)&sKl[r * AS + cs + 8 * u] = *(const uint4*)(kl + 8 * u);
                *(uint4*)&sVh[r * AS + cs + 8 * u] = *(const uint4*)(vh + 8 * u);
                *(uint4*)&sVl[r * AS + cs + 8 * u] = *(const uint4*)(vl + 8 * u);
            }
        }
        __syncthreads();

        // ---- S = Q @ K^T (split-3) ----
        float sc[8][4];
#pragma unroll
        for (int na = 0; na < 8; na++)
#pragma unroll
            for (int v = 0; v < 4; v++) sc[na][v] = 0.0f;

#pragma unroll
        for (int kk = 0; kk < 4; kk++) {
            uint32_t qh[4], ql[4];
            ldsm4(qh, aQh + kk * 32);
            ldsm4(ql, aQl + kk * 32);
#pragma unroll
            for (int half = 0; half < 2; half++) {
                uint32_t kh0[4], kh1[4], kl0[4], kl1[4];
                ldsm4(kh0, aKh[half * 2 + 0] + kk * 32);
                ldsm4(kh1, aKh[half * 2 + 1] + kk * 32);
                ldsm4(kl0, aKl[half * 2 + 0] + kk * 32);
                ldsm4(kl1, aKl[half * 2 + 1] + kk * 32);
                mma3(sc[half * 4 + 0], qh, ql, kh0[0], kh0[2], kl0[0], kl0[2]);
                mma3(sc[half * 4 + 1], qh, ql, kh0[1], kh0[3], kl0[1], kl0[3]);
                mma3(sc[half * 4 + 2], qh, ql, kh1[0], kh1[2], kl1[0], kl1[2]);
                mma3(sc[half * 4 + 3], qh, ql, kh1[1], kh1[3], kl1[1], kl1[3]);
            }
        }

        // ---- warp-local online softmax ----
        float rm0 = -1e30f, rm1 = -1e30f;
#pragma unroll
        for (int na = 0; na < 8; na++) {
            rm0 = fmaxf(rm0, fmaxf(sc[na][0], sc[na][1]));
            rm1 = fmaxf(rm1, fmaxf(sc[na][2], sc[na][3]));
        }
#pragma unroll
        for (int off = 1; off < 4; off <<= 1) {
            rm0 = fmaxf(rm0, __shfl_xor_sync(0xffffffffu, rm0, off));
            rm1 = fmaxf(rm1, __shfl_xor_sync(0xffffffffu, rm1, off));
        }
        const float mn0 = fmaxf(m0r, rm0), mn1 = fmaxf(m1r, rm1);
        const float cor0 = __expf(m0r - mn0), cor1 = __expf(m1r - mn1);
        float rs0 = 0.0f, rs1 = 0.0f;
#pragma unroll
        for (int na = 0; na < 8; na++) {
            sc[na][0] = __expf(sc[na][0] - mn0);
            sc[na][1] = __expf(sc[na][1] - mn0);
            sc[na][2] = __expf(sc[na][2] - mn1);
            sc[na][3] = __expf(sc[na][3] - mn1);
            rs0 += sc[na][0] + sc[na][1];
            rs1 += sc[na][2] + sc[na][3];
        }
#pragma unroll
        for (int off = 1; off < 4; off <<= 1) {
            rs0 += __shfl_xor_sync(0xffffffffu, rs0, off);
            rs1 += __shfl_xor_sync(0xffffffffu, rs1, off);
        }
        l0r = l0r * cor0 + rs0;
        l1r = l1r * cor1 + rs1;
        m0r = mn0; m1r = mn1;
#pragma unroll
        for (int na = 0; na < 8; na++) {
            o[na][0] *= cor0; o[na][1] *= cor0;
            o[na][2] *= cor1; o[na][3] *= cor1;
        }

        // ---- O += P @ V (split-3; P fragments straight from registers) ----
#pragma unroll
        for (int kk = 0; kk < 4; kk++) {
            uint32_t pah[4], pal[4];
            {
                bf16 h0, h1, l0, l1;
                bsplit(sc[2 * kk][0], h0, l0); bsplit(sc[2 * kk][1], h1, l1);
                pah[0] = pk(h0, h1); pal[0] = pk(l0, l1);
                bsplit(sc[2 * kk][2], h0, l0); bsplit(sc[2 * kk][3], h1, l1);
                pah[1] = pk(h0, h1); pal[1] = pk(l0, l1);
                bsplit(sc[2 * kk + 1][0], h0, l0); bsplit(sc[2 * kk + 1][1], h1, l1);
                pah[2] = pk(h0, h1); pal[2] = pk(l0, l1);
                bsplit(sc[2 * kk + 1][2], h0, l0); bsplit(sc[2 * kk + 1][3], h1, l1);
                pah[3] = pk(h0, h1); pal[3] = pk(l0, l1);
            }
#pragma unroll
            for (int half = 0; half < 2; half++) {
                uint32_t vh0[4], vh1[4], vl0[4], vl1[4];
                ldsm4(vh0, aVh[half * 2 + 0] + kk * 32);
                ldsm4(vh1, aVh[half * 2 + 1] + kk * 32);
                ldsm4(vl0, aVl[half * 2 + 0] + kk * 32);
                ldsm4(vl1, aVl[half * 2 + 1] + kk * 32);
                mma3(o[half * 4 + 0], pah, pal, vh0[0], vh0[2], vl0[0], vl0[2]);
                mma3(o[half * 4 + 1], pah, pal, vh0[1], vh0[3], vl0[1], vl0[3]);
                mma3(o[half * 4 + 2], pah, pal, vh1[0], vh1[2], vl1[0], vl1[2]);
                mma3(o[half * 4 + 3], pah, pal, vh1[1], vh1[3], vl1[1], vl1[3]);
            }
        }
    }

    // epilogue: atn[b, s, d*H + h] = O / l
    {
        const float inv0 = 1.0f / l0r, inv1 = 1.0f / l1r;
        const int s0 = q0 + wq + g, s1 = s0 + 8;
        float* d0 = g_atn + ((size_t)(b * S_ + s0)) * D_;
        float* d1 = g_atn + ((size_t)(b * S_ + s1)) * D_;
#pragma unroll
        for (int na = 0; na < 8; na++) {
            const int dd = na * 8 + 2 * l4;
            d0[dd * H_ + hh]       = o[na][0] * inv0;
            d0[(dd + 1) * H_ + hh] = o[na][1] * inv0;
            d1[dd * H_ + hh]       = o[na][2] * inv1;
            d1[(dd + 1) * H_ + hh] = o[na][3] * inv1;
        }
    }
}

// ---------------------------------------------------------------------------
extern "C" void kernel_launch(void* const* d_in, const int* in_sizes, int n_in,
                              void* d_out, int out_size)
{
    const float* xs    = (const float*)d_in[0];
    // d_in[1] = mask (all-true) — unused
    const float* w_qkv = (const float*)d_in[2];
    const float* w_out = (const float*)d_in[3];
    float* out = (float*)d_out;

    bf16 *Xh, *Xl, *Wqh, *Wql, *Woh, *Wol, *Aih, *Ail;
    float* atn_ptr;
    cudaGetSymbolAddress((void**)&Xh,  g_Xh);
    cudaGetSymbolAddress((void**)&Xl,  g_Xl);
    cudaGetSymbolAddress((void**)&Wqh, g_Wqh);
    cudaGetSymbolAddress((void**)&Wql, g_Wql);
    cudaGetSymbolAddress((void**)&Woh, g_Woh);
    cudaGetSymbolAddress((void**)&Wol, g_Wol);
    cudaGetSymbolAddress((void**)&Aih, g_Aih);
    cudaGetSymbolAddress((void**)&Ail, g_Ail);
    cudaGetSymbolAddress((void**)&atn_ptr, g_atn);

    // 0) pre-split inputs to bf16 hi/lo
    split_kernel<<<(M_ * D_) / 1024, 256>>>(xs, Xh, Xl, M_ * D_);
    split_kernel<<<(3 * D_ * D_) / 1024, 256>>>(w_qkv, Wqh, Wql, 3 * D_ * D_);
    split_kernel<<<(D_ * D_) / 1024, 256>>>(w_out, Woh, Wol, D_ * D_);

    // 1) QKV projection with scatter epilogue
    {
        dim3 grid(3 * D_ / 128, M_ / 128);  // (24, 32)
        gemm_bf16<1><<<grid, 256>>>(Xh, Xl, Wqh, Wql, nullptr, M_, 3 * D_, D_);
    }

    // 2) flash attention
    {
        const int smem = (2 * 128 + 4 * 64) * AS * 2;  // 73728 B
        cudaFuncSetAttribute(attn_bf16,
                             cudaFuncAttributeMaxDynamicSharedMemorySize, smem);
        dim3 grid(S_ / 128, H_, B_);  // (16, 16, 2)
        attn_bf16<<<grid, 256, smem>>>();
    }

    // 3) split attention output, then out-projection
    split_kernel<<<(M_ * D_) / 1024, 256>>>(atn_ptr, Aih, Ail, M_ * D_);
    {
        dim3 grid(D_ / 128, M_ / 128);  // (8, 32)
        gemm_bf16<0><<<grid, 256>>>(Aih, Ail, Woh, Wol, out, M_, D_, D_);
    }
}

// round 4
// speedup vs baseline: 2.0339x; 1.0817x over previous
#include <cuda_runtime.h>
#include <cuda_bf16.h>
#include <cstdint>

#define H_ 16
#define D_ 1024
#define DK 64
#define B_ 2
#define S_ 2048
#define M_ (B_ * S_)   // 4096

typedef __nv_bfloat16 bf16;

// ---------------- device scratch ----------------
__device__ bf16 g_Xh [M_ * D_],     g_Xl [M_ * D_];
__device__ bf16 g_Wqh[3 * D_ * D_], g_Wql[3 * D_ * D_];
__device__ bf16 g_Woh[D_ * D_],     g_Wol[D_ * D_];
__device__ bf16 g_Aih[M_ * D_],     g_Ail[M_ * D_];
__device__ bf16 g_Qh[B_*H_*S_*DK],  g_Ql[B_*H_*S_*DK];   // pre-scaled 1/8
__device__ bf16 g_Kh[B_*H_*S_*DK],  g_Kl[B_*H_*S_*DK];
__device__ bf16 g_Vh[B_*H_*DK*S_],  g_Vl[B_*H_*DK*S_];   // V^T [b,h,d,s]
__device__ float g_atn[M_ * D_];                          // ch = d*H+h

// ---------------- helpers ----------------
__device__ __forceinline__ void bsplit(float x, bf16& h, bf16& l) {
    h = __float2bfloat16(x);
    l = __float2bfloat16(x - __bfloat162float(h));
}
__device__ __forceinline__ uint32_t pk(bf16 a, bf16 b) {
    return (uint32_t)__bfloat16_as_ushort(a) |
           ((uint32_t)__bfloat16_as_ushort(b) << 16);
}
__device__ __forceinline__ uint32_t smem_u32(const void* p) {
    return (uint32_t)__cvta_generic_to_shared(p);
}
__device__ __forceinline__ void ldsm4(uint32_t r[4], uint32_t addr) {
    asm volatile("ldmatrix.sync.aligned.m8n8.x4.shared.b16 {%0,%1,%2,%3}, [%4];"
                 : "=r"(r[0]), "=r"(r[1]), "=r"(r[2]), "=r"(r[3]) : "r"(addr));
}
__device__ __forceinline__ void mma_bf16(float c[4], const uint32_t a[4],
                                         uint32_t b0, uint32_t b1) {
    asm volatile(
        "mma.sync.aligned.m16n8k16.row.col.f32.bf16.bf16.f32 "
        "{%0,%1,%2,%3}, {%4,%5,%6,%7}, {%8,%9}, {%0,%1,%2,%3};\n"
        : "+f"(c[0]), "+f"(c[1]), "+f"(c[2]), "+f"(c[3])
        : "r"(a[0]), "r"(a[1]), "r"(a[2]), "r"(a[3]), "r"(b0), "r"(b1));
}
__device__ __forceinline__ void mma3(float c[4], const uint32_t ah[4],
                                     const uint32_t al[4],
                                     uint32_t bh0, uint32_t bh1,
                                     uint32_t bl0, uint32_t bl1) {
    mma_bf16(c, ah, bh0, bh1);
    mma_bf16(c, ah, bl0, bl1);
    mma_bf16(c, al, bh0, bh1);
}
__device__ __forceinline__ void cpa16(uint32_t saddr, const void* g) {
    asm volatile("cp.async.cg.shared.global [%0], [%1], 16;"
                 :: "r"(saddr), "l"(g));
}
__device__ __forceinline__ void cp_commit() {
    asm volatile("cp.async.commit_group;");
}
template <int N>
__device__ __forceinline__ void cp_wait() {
    asm volatile("cp.async.wait_group %0;" :: "n"(N));
}

// ---------------- pre-split pass ----------------
__global__ __launch_bounds__(256) void split_kernel(
    const float* __restrict__ x, bf16* __restrict__ h, bf16* __restrict__ l, int n)
{
    const int i = (blockIdx.x * 256 + threadIdx.x) * 4;
    if (i >= n) return;
    float4 v = *(const float4*)(x + i);
    bf16 h0, h1, h2, h3, l0, l1, l2, l3;
    bsplit(v.x, h0, l0); bsplit(v.y, h1, l1);
    bsplit(v.z, h2, l2); bsplit(v.w, h3, l3);
    *(uint32_t*)(h + i)     = pk(h0, h1);
    *(uint32_t*)(h + i + 2) = pk(h2, h3);
    *(uint32_t*)(l + i)     = pk(l0, l1);
    *(uint32_t*)(l + i + 2) = pk(l2, l3);
}

// ---------------------------------------------------------------------------
// bf16 split-3 GEMM with 3-stage cp.async pipeline.
// Block 128x128, BK=16, 256 thr, 8 warps (4Mx2N), warp tile 32x64.
// smem/stage: 4 arrays x 128 x GS bf16.  3 stages = 73728 B (dynamic).
// ---------------------------------------------------------------------------
#define GS 24
#define GAR (128 * GS)           // elements per array
#define GARB (GAR * 2)           // bytes per array (6144)
#define GSGB (4 * GARB)          // bytes per stage (24576)
template <int MODE>
__global__ __launch_bounds__(256, 2) void gemm_bf16(
    const bf16* __restrict__ Ah, const bf16* __restrict__ Al,
    const bf16* __restrict__ Bh, const bf16* __restrict__ Bl,
    float* __restrict__ C, int M, int N, int K)
{
    extern __shared__ __align__(16) bf16 sm[];

    const int t = threadIdx.x, lane = t & 31, wid = t >> 5;
    const int g = lane >> 2, l4 = lane & 3;
    const int warpM = wid >> 1, warpN = wid & 1;
    const int m0 = blockIdx.y * 128, n0 = blockIdx.x * 128;

    float c[2][8][4];
#pragma unroll
    for (int i = 0; i < 2; i++)
#pragma unroll
        for (int j = 0; j < 8; j++)
#pragma unroll
            for (int v = 0; v < 4; v++) c[i][j][v] = 0.0f;

    // staging addresses: 1 x 16B chunk per array per stage per thread
    const int srow = t >> 1, sseg = (t & 1) * 8;
    const bf16* pAh = Ah + (size_t)(m0 + srow) * K + sseg;
    const bf16* pAl = Al + (size_t)(m0 + srow) * K + sseg;
    const bf16* pBh = Bh + (size_t)(n0 + srow) * K + sseg;
    const bf16* pBl = Bl + (size_t)(n0 + srow) * K + sseg;
    const uint32_t stBase = smem_u32(&sm[srow * GS + sseg]);

    // ldmatrix stage-0 byte addresses
    const int fr = lane & 15, fc = (lane >> 4) * 8;
    uint32_t aA[2];
#pragma unroll
    for (int ma = 0; ma < 2; ma++)
        aA[ma] = smem_u32(&sm[(warpM * 32 + ma * 16 + fr) * GS + fc]);
    uint32_t aB[4];
#pragma unroll
    for (int hq = 0; hq < 4; hq++)
        aB[hq] = smem_u32(&sm[(warpN * 64 + hq * 16 + fr) * GS + fc]) + 2 * GARB;

    const int KT = K / 16;

    // preload stages 0,1
#pragma unroll
    for (int s = 0; s < 2; s++) {
        const int k0 = s * 16;
        const uint32_t sb = stBase + s * GSGB;
        cpa16(sb + 0 * GARB, pAh + k0);
        cpa16(sb + 1 * GARB, pAl + k0);
        cpa16(sb + 2 * GARB, pBh + k0);
        cpa16(sb + 3 * GARB, pBl + k0);
        cp_commit();
    }

    int st = 0;   // current compute stage
    for (int kt = 0; kt < KT; kt++) {
        cp_wait<1>();
        __syncthreads();

        // issue loads for stage kt+2 (overwrites stage computed at kt-1)
        if (kt + 2 < KT) {
            int s2 = st + 2; if (s2 >= 3) s2 -= 3;
            const int k0 = (kt + 2) * 16;
            const uint32_t sb = stBase + s2 * GSGB;
            cpa16(sb + 0 * GARB, pAh + k0);
            cpa16(sb + 1 * GARB, pAl + k0);
            cpa16(sb + 2 * GARB, pBh + k0);
            cpa16(sb + 3 * GARB, pBl + k0);
        }
        cp_commit();

        const uint32_t sb = st * GSGB;
        uint32_t fAh[2][4], fAl[2][4];
        ldsm4(fAh[0], aA[0] + sb); ldsm4(fAh[1], aA[1] + sb);
        ldsm4(fAl[0], aA[0] + sb + GARB); ldsm4(fAl[1], aA[1] + sb + GARB);

#pragma unroll
        for (int half = 0; half < 2; half++) {
            uint32_t bh0[4], bh1[4], bl0[4], bl1[4];
            ldsm4(bh0, aB[half * 2 + 0] + sb);
            ldsm4(bh1, aB[half * 2 + 1] + sb);
            ldsm4(bl0, aB[half * 2 + 0] + sb + GARB);
            ldsm4(bl1, aB[half * 2 + 1] + sb + GARB);
#pragma unroll
            for (int ma = 0; ma < 2; ma++) {
                mma3(c[ma][half * 4 + 0], fAh[ma], fAl[ma], bh0[0], bh0[2], bl0[0], bl0[2]);
                mma3(c[ma][half * 4 + 1], fAh[ma], fAl[ma], bh0[1], bh0[3], bl0[1], bl0[3]);
                mma3(c[ma][half * 4 + 2], fAh[ma], fAl[ma], bh1[0], bh1[2], bl1[0], bl1[2]);
                mma3(c[ma][half * 4 + 3], fAh[ma], fAl[ma], bh1[1], bh1[3], bl1[1], bl1[3]);
            }
        }
        if (++st == 3) st = 0;
    }

    // epilogue
#pragma unroll
    for (int ma = 0; ma < 2; ma++)
#pragma unroll
        for (int na = 0; na < 8; na++)
#pragma unroll
            for (int v = 0; v < 4; v++) {
                const int m = m0 + warpM * 32 + ma * 16 + g + ((v >= 2) ? 8 : 0);
                const int n = n0 + warpN * 64 + na * 8 + 2 * l4 + (v & 1);
                const float val = c[ma][na][v];
                if (MODE == 0) {
                    C[(size_t)m * N + n] = val;
                } else {
                    const int s = m & (S_ - 1), b = m >> 11;
                    const int sel = n >> 10, e = n & 1023;
                    const int hh = e & 15, d = e >> 4;
                    bf16 hi, lo;
                    if (sel == 2) {
                        bsplit(val, hi, lo);
                        const size_t vi = (((size_t)(b * H_ + hh)) * DK + d) * S_ + s;
                        g_Vh[vi] = hi; g_Vl[vi] = lo;
                    } else {
                        const size_t idx = (((size_t)(b * H_ + hh)) * S_ + s) * DK + d;
                        if (sel == 0) {
                            bsplit(val * 0.125f, hi, lo);
                            g_Qh[idx] = hi; g_Ql[idx] = lo;
                        } else {
                            bsplit(val, hi, lo);
                            g_Kh[idx] = hi; g_Kl[idx] = lo;
                        }
                    }
                }
            }
}

// ---------------------------------------------------------------------------
// Flash attention, bf16 split-3, q-tile 128, kv-tile 64, 2-stage cp.async K/V.
// smem: Qh/Ql 128xAS each, then 2 stages x {Kh,Kl,Vh,Vl} 64xAS. 110592 B.
// ---------------------------------------------------------------------------
#define AS 72
#define QAR (128 * AS)
#define KVAR (64 * AS)
#define KVARB (KVAR * 2)          // 9216 B per array
#define KVSGB (4 * KVARB)         // 36864 B per stage
__global__ __launch_bounds__(256, 2) void attn_bf16()
{
    extern __shared__ __align__(16) bf16 sm[];
    bf16* sQh = sm;
    bf16* sQl = sm + QAR;
    bf16* sKV = sm + 2 * QAR;     // stage base

    const int t = threadIdx.x, lane = t & 31, wid = t >> 5;
    const int g = lane >> 2, l4 = lane & 3;
    const int qt = blockIdx.x, hh = blockIdx.y, b = blockIdx.z;
    const int bhid = b * H_ + hh;
    const int q0 = qt * 128;
    const int wq = wid * 16;

    // stage Q (hi/lo) once via cp.async
    {
        const int row = t >> 1, cs = (t & 1) * 32;
        const bf16* gqh = g_Qh + ((size_t)bhid * S_ + q0 + row) * DK + cs;
        const bf16* gql = g_Ql + ((size_t)bhid * S_ + q0 + row) * DK + cs;
        const uint32_t dqh = smem_u32(&sQh[row * AS + cs]);
        const uint32_t dql = smem_u32(&sQl[row * AS + cs]);
#pragma unroll
        for (int u = 0; u < 4; u++) {
            cpa16(dqh + 16 * u, gqh + 8 * u);
            cpa16(dql + 16 * u, gql + 8 * u);
        }
    }

    // K/V staging addresses (per thread: 2 x 16B per array per stage)
    const int kr = t >> 2, kcs = (t & 3) * 16;
    const bf16* gkh = g_Kh + ((size_t)bhid * S_ + kr) * DK + kcs;
    const bf16* gkl = g_Kl + ((size_t)bhid * S_ + kr) * DK + kcs;
    const bf16* gvh = g_Vh + ((size_t)bhid * DK + kr) * S_ + kcs;
    const bf16* gvl = g_Vl + ((size_t)bhid * DK + kr) * S_ + kcs;
    const uint32_t kvBase = smem_u32(&sKV[kr * AS + kcs]);

    // preload stage 0 (jt = 0): K offset = jt*64*DK rows, V offset = jt*64 cols
#pragma unroll
    for (int u = 0; u < 2; u++) {
        cpa16(kvBase + 0 * KVARB + 16 * u, gkh + 8 * u);
        cpa16(kvBase + 1 * KVARB + 16 * u, gkl + 8 * u);
        cpa16(kvBase + 2 * KVARB + 16 * u, gvh + 8 * u);
        cpa16(kvBase + 3 * KVARB + 16 * u, gvl + 8 * u);
    }
    cp_commit();

    // ldmatrix addresses
    const int fr = lane & 15, fc = (lane >> 4) * 8;
    const uint32_t aQh = smem_u32(&sQh[(wq + fr) * AS + fc]);
    const uint32_t aQl = smem_u32(&sQl[(wq + fr) * AS + fc]);
    uint32_t aK[4], aV[4];
#pragma unroll
    for (int hq = 0; hq < 4; hq++) {
        const uint32_t rowb = smem_u32(&sKV[(hq * 16 + fr) * AS + fc]);
        aK[hq] = rowb;                 // +KVARB for lo
        aV[hq] = rowb + 2 * KVARB;     // +KVARB for lo
    }

    float o[8][4];
#pragma unroll
    for (int na = 0; na < 8; na++)
#pragma unroll
        for (int v = 0; v < 4; v++) o[na][v] = 0.0f;
    float m0r = -1e30f, m1r = -1e30f, l0r = 0.0f, l1r = 0.0f;

    const int NT = S_ / 64;
    for (int jt = 0; jt < NT; jt++) {
        cp_wait<0>();
        __syncthreads();

        // issue loads for jt+1 into other stage
        if (jt + 1 < NT) {
            const uint32_t sb = kvBase + ((jt + 1) & 1) * KVSGB;
            const int kro = (jt + 1) * 64 * DK;   // K rows advance
            const int vco = (jt + 1) * 64;        // V cols advance
#pragma unroll
            for (int u = 0; u < 2; u++) {
                cpa16(sb + 0 * KVARB + 16 * u, gkh + kro + 8 * u);
                cpa16(sb + 1 * KVARB + 16 * u, gkl + kro + 8 * u);
                cpa16(sb + 2 * KVARB + 16 * u, gvh + vco + 8 * u);
                cpa16(sb + 3 * KVARB + 16 * u, gvl + vco + 8 * u);
            }
        }
        cp_commit();

        const uint32_t sb = (jt & 1) * KVSGB;

        // ---- S = Q @ K^T (split-3) ----
        float sc[8][4];
#pragma unroll
        for (int na = 0; na < 8; na++)
#pragma unroll
            for (int v = 0; v < 4; v++) sc[na][v] = 0.0f;

#pragma unroll
        for (int kk = 0; kk < 4; kk++) {
            uint32_t qh[4], ql[4];
            ldsm4(qh, aQh + kk * 32);
            ldsm4(ql, aQl + kk * 32);
#pragma unroll
            for (int half = 0; half < 2; half++) {
                uint32_t kh0[4], kh1[4], kl0[4], kl1[4];
                ldsm4(kh0, aK[half * 2 + 0] + sb + kk * 32);
                ldsm4(kh1, aK[half * 2 + 1] + sb + kk * 32);
                ldsm4(kl0, aK[half * 2 + 0] + sb + KVARB + kk * 32);
                ldsm4(kl1, aK[half * 2 + 1] + sb + KVARB + kk * 32);
                mma3(sc[half * 4 + 0], qh, ql, kh0[0], kh0[2], kl0[0], kl0[2]);
                mma3(sc[half * 4 + 1], qh, ql, kh0[1], kh0[3], kl0[1], kl0[3]);
                mma3(sc[half * 4 + 2], qh, ql, kh1[0], kh1[2], kl1[0], kl1[2]);
                mma3(sc[half * 4 + 3], qh, ql, kh1[1], kh1[3], kl1[1], kl1[3]);
            }
        }

        // ---- warp-local online softmax ----
        float rm0 = -1e30f, rm1 = -1e30f;
#pragma unroll
        for (int na = 0; na < 8; na++) {
            rm0 = fmaxf(rm0, fmaxf(sc[na][0], sc[na][1]));
            rm1 = fmaxf(rm1, fmaxf(sc[na][2], sc[na][3]));
        }
#pragma unroll
        for (int off = 1; off < 4; off <<= 1) {
            rm0 = fmaxf(rm0, __shfl_xor_sync(0xffffffffu, rm0, off));
            rm1 = fmaxf(rm1, __shfl_xor_sync(0xffffffffu, rm1, off));
        }
        const float mn0 = fmaxf(m0r, rm0), mn1 = fmaxf(m1r, rm1);
        const float cor0 = __expf(m0r - mn0), cor1 = __expf(m1r - mn1);
        float rs0 = 0.0f, rs1 = 0.0f;
#pragma unroll
        for (int na = 0; na < 8; na++) {
            sc[na][0] = __expf(sc[na][0] - mn0);
            sc[na][1] = __expf(sc[na][1] - mn0);
            sc[na][2] = __expf(sc[na][2] - mn1);
            sc[na][3] = __expf(sc[na][3] - mn1);
            rs0 += sc[na][0] + sc[na][1];
            rs1 += sc[na][2] + sc[na][3];
        }
#pragma unroll
        for (int off = 1; off < 4; off <<= 1) {
            rs0 += __shfl_xor_sync(0xffffffffu, rs0, off);
            rs1 += __shfl_xor_sync(0xffffffffu, rs1, off);
        }
        l0r = l0r * cor0 + rs0;
        l1r = l1r * cor1 + rs1;
        m0r = mn0; m1r = mn1;
#pragma unroll
        for (int na = 0; na < 8; na++) {
            o[na][0] *= cor0; o[na][1] *= cor0;
            o[na][2] *= cor1; o[na][3] *= cor1;
        }

        // ---- O += P @ V (split-3, P from registers) ----
#pragma unroll
        for (int kk = 0; kk < 4; kk++) {
            uint32_t pah[4], pal[4];
            {
                bf16 h0, h1, l0, l1;
                bsplit(sc[2 * kk][0], h0, l0); bsplit(sc[2 * kk][1], h1, l1);
                pah[0] = pk(h0, h1); pal[0] = pk(l0, l1);
                bsplit(sc[2 * kk][2], h0, l0); bsplit(sc[2 * kk][3], h1, l1);
                pah[1] = pk(h0, h1); pal[1] = pk(l0, l1);
                bsplit(sc[2 * kk + 1][0], h0, l0); bsplit(sc[2 * kk + 1][1], h1, l1);
                pah[2] = pk(h0, h1); pal[2] = pk(l0, l1);
                bsplit(sc[2 * kk + 1][2], h0, l0); bsplit(sc[2 * kk + 1][3], h1, l1);
                pah[3] = pk(h0, h1); pal[3] = pk(l0, l1);
            }
#pragma unroll
            for (int half = 0; half < 2; half++) {
                uint32_t vh0[4], vh1[4], vl0[4], vl1[4];
                ldsm4(vh0, aV[half * 2 + 0] + sb + kk * 32);
                ldsm4(vh1, aV[half * 2 + 1] + sb + kk * 32);
                ldsm4(vl0, aV[half * 2 + 0] + sb + KVARB + kk * 32);
                ldsm4(vl1, aV[half * 2 + 1] + sb + KVARB + kk * 32);
                mma3(o[half * 4 + 0], pah, pal, vh0[0], vh0[2], vl0[0], vl0[2]);
                mma3(o[half * 4 + 1], pah, pal, vh0[1], vh0[3], vl0[1], vl0[3]);
                mma3(o[half * 4 + 2], pah, pal, vh1[0], vh1[2], vl1[0], vl1[2]);
                mma3(o[half * 4 + 3], pah, pal, vh1[1], vh1[3], vl1[1], vl1[3]);
            }
        }
    }

    // epilogue: atn[b, s, d*H + h] = O / l
    {
        const float inv0 = 1.0f / l0r, inv1 = 1.0f / l1r;
        const int s0 = q0 + wq + g, s1 = s0 + 8;
        float* d0 = g_atn + ((size_t)(b * S_ + s0)) * D_;
        float* d1 = g_atn + ((size_t)(b * S_ + s1)) * D_;
#pragma unroll
        for (int na = 0; na < 8; na++) {
            const int dd = na * 8 + 2 * l4;
            d0[dd * H_ + hh]       = o[na][0] * inv0;
            d0[(dd + 1) * H_ + hh] = o[na][1] * inv0;
            d1[dd * H_ + hh]       = o[na][2] * inv1;
            d1[(dd + 1) * H_ + hh] = o[na][3] * inv1;
        }
    }
}

// ---------------------------------------------------------------------------
extern "C" void kernel_launch(void* const* d_in, const int* in_sizes, int n_in,
                              void* d_out, int out_size)
{
    const float* xs    = (const float*)d_in[0];
    const float* w_qkv = (const float*)d_in[2];
    const float* w_out = (const float*)d_in[3];
    float* out = (float*)d_out;

    bf16 *Xh, *Xl, *Wqh, *Wql, *Woh, *Wol, *Aih, *Ail;
    float* atn_ptr;
    cudaGetSymbolAddress((void**)&Xh,  g_Xh);
    cudaGetSymbolAddress((void**)&Xl,  g_Xl);
    cudaGetSymbolAddress((void**)&Wqh, g_Wqh);
    cudaGetSymbolAddress((void**)&Wql, g_Wql);
    cudaGetSymbolAddress((void**)&Woh, g_Woh);
    cudaGetSymbolAddress((void**)&Wol, g_Wol);
    cudaGetSymbolAddress((void**)&Aih, g_Aih);
    cudaGetSymbolAddress((void**)&Ail, g_Ail);
    cudaGetSymbolAddress((void**)&atn_ptr, g_atn);

    const int gemm_smem = 3 * GSGB;          // 73728
    cudaFuncSetAttribute(gemm_bf16<0>,
                         cudaFuncAttributeMaxDynamicSharedMemorySize, gemm_smem);
    cudaFuncSetAttribute(gemm_bf16<1>,
                         cudaFuncAttributeMaxDynamicSharedMemorySize, gemm_smem);

    // 0) pre-split inputs
    split_kernel<<<(M_ * D_) / 1024, 256>>>(xs, Xh, Xl, M_ * D_);
    split_kernel<<<(3 * D_ * D_) / 1024, 256>>>(w_qkv, Wqh, Wql, 3 * D_ * D_);
    split_kernel<<<(D_ * D_) / 1024, 256>>>(w_out, Woh, Wol, D_ * D_);

    // 1) QKV projection
    {
        dim3 grid(3 * D_ / 128, M_ / 128);
        gemm_bf16<1><<<grid, 256, gemm_smem>>>(Xh, Xl, Wqh, Wql, nullptr,
                                               M_, 3 * D_, D_);
    }

    // 2) flash attention
    {
        const int smem = (2 * QAR) * 2 + 2 * KVSGB;  // 110592
        cudaFuncSetAttribute(attn_bf16,
                             cudaFuncAttributeMaxDynamicSharedMemorySize, smem);
        dim3 grid(S_ / 128, H_, B_);
        attn_bf16<<<grid, 256, smem>>>();
    }

    // 3) out-projection
    split_kernel<<<(M_ * D_) / 1024, 256>>>(atn_ptr, Aih, Ail, M_ * D_);
    {
        dim3 grid(D_ / 128, M_ / 128);
        gemm_bf16<0><<<grid, 256, gemm_smem>>>(Aih, Ail, Woh, Wol, out,
                                               M_, D_, D_);
    }
}